// round 11
// baseline (speedup 1.0000x reference)
#include <cuda_runtime.h>
#include <cuda_bf16.h>
#include <math_constants.h>
#include <cstdint>

#define NN 50000
#define EE 600000
#define DD 128
#define LL 12
#define GRID_G ((NN + 127) / 128)   // 391
#define AGG_BLOCKS ((NN + 7) / 8)   // 6250

#define SROW 40
#define ABYTES (128 * SROW * 2)          // 10240 B per 128x32 bf16 array
#define STAGE_BYTES (4 * ABYTES)         // Ahi,Alo,Bhi,Blo
#define TG_SMEM (2 * STAGE_BYTES + 512)

#define AGG_SMEM (8 * 2 * 4096)          // 8 warps x 2 bufs x 8 rows x 512B = 64KB

// ---------------- persistent device scratch ----------------
__device__ float g_h0[NN * DD];
__device__ float g_h1[NN * DD];
__device__ float g_hm[NN * DD];
__device__ __nv_bfloat16 g_aggHi[NN * 128];
__device__ __nv_bfloat16 g_aggLo[NN * 128];
__device__ __nv_bfloat16 g_Bhi[LL * 128 * 256];
__device__ __nv_bfloat16 g_Blo[LL * 128 * 256];
__device__ __nv_bfloat16 g_W1hi[128 * 128];
__device__ __nv_bfloat16 g_W1lo[128 * 128];
__device__ int g_rowptr[NN + 1];
__device__ int g_woff[NN];
__device__ int g_csrc[EE];
__device__ int g_deg[NN];
__device__ int g_part[256];
__device__ int g_partscan[256];

// ---------------- helpers ----------------
__device__ __forceinline__ uint32_t s2u(const void* p) {
    uint32_t a;
    asm("{ .reg .u64 t; cvta.to.shared.u64 t, %1; cvt.u32.u64 %0, t; }" : "=r"(a) : "l"(p));
    return a;
}
__device__ __forceinline__ void ldsm4(uint32_t& r0, uint32_t& r1, uint32_t& r2, uint32_t& r3,
                                      uint32_t addr) {
    asm volatile("ldmatrix.sync.aligned.m8n8.x4.shared.b16 {%0,%1,%2,%3}, [%4];"
                 : "=r"(r0), "=r"(r1), "=r"(r2), "=r"(r3) : "r"(addr));
}
__device__ __forceinline__ void mmabf(float* c, const uint32_t* a, uint32_t b0, uint32_t b1) {
    asm volatile(
        "mma.sync.aligned.m16n8k16.row.col.f32.bf16.bf16.f32 "
        "{%0,%1,%2,%3}, {%4,%5,%6,%7}, {%8,%9}, {%0,%1,%2,%3};"
        : "+f"(c[0]), "+f"(c[1]), "+f"(c[2]), "+f"(c[3])
        : "r"(a[0]), "r"(a[1]), "r"(a[2]), "r"(a[3]), "r"(b0), "r"(b1));
}
__device__ __forceinline__ uint32_t pack2bf(float a, float b) {
    __nv_bfloat16 ha = __float2bfloat16(a), hb = __float2bfloat16(b);
    return ((uint32_t)__bfloat16_as_ushort(hb) << 16) | (uint32_t)__bfloat16_as_ushort(ha);
}
__device__ __forceinline__ void cpasync16(uint32_t dst, const void* src) {
    asm volatile("cp.async.cg.shared.global [%0], [%1], 16;" :: "r"(dst), "l"(src));
}

// ---------------- CSR build ----------------
__global__ void k_zero_deg() {
    int i = blockIdx.x * blockDim.x + threadIdx.x;
    if (i < NN) g_deg[i] = 0;
}
__global__ void k_hist(const int* __restrict__ ei) {
    int e = blockIdx.x * blockDim.x + threadIdx.x;
    if (e < EE) atomicAdd(&g_deg[ei[EE + e]], 1);
}
__global__ void k_blocksum() {
    __shared__ int sm[256];
    int t = threadIdx.x;
    int i = blockIdx.x * 256 + t;
    sm[t] = (i < NN) ? g_deg[i] : 0;
    __syncthreads();
    for (int o = 128; o > 0; o >>= 1) {
        if (t < o) sm[t] += sm[t + o];
        __syncthreads();
    }
    if (t == 0) g_part[blockIdx.x] = sm[0];
}
__global__ void k_scanpart() {
    __shared__ int sm[256];
    int t = threadIdx.x;
    int v = (t < 196) ? g_part[t] : 0;
    sm[t] = v;
    __syncthreads();
    for (int o = 1; o < 256; o <<= 1) {
        int u = (t >= o) ? sm[t - o] : 0;
        __syncthreads();
        sm[t] += u;
        __syncthreads();
    }
    g_partscan[t] = sm[t] - v;
    if (t == 0) g_rowptr[NN] = EE;
}
__global__ void k_rowptr() {
    __shared__ int sm[256];
    int t = threadIdx.x;
    int i = blockIdx.x * 256 + t;
    int v = (i < NN) ? g_deg[i] : 0;
    sm[t] = v;
    __syncthreads();
    for (int o = 1; o < 256; o <<= 1) {
        int u = (t >= o) ? sm[t - o] : 0;
        __syncthreads();
        sm[t] += u;
        __syncthreads();
    }
    if (i < NN) {
        int ex = g_partscan[blockIdx.x] + sm[t] - v;
        g_rowptr[i] = ex;
        g_woff[i] = ex;
    }
}
__global__ void k_fill(const int* __restrict__ ei) {
    int e = blockIdx.x * blockDim.x + threadIdx.x;
    if (e < EE) {
        int d = ei[EE + e];
        int p = atomicAdd(&g_woff[d], 1);
        g_csrc[p] = ei[e];
    }
}

// ---------------- weight split preprocessing ----------------
__global__ void k_wprep(const float* __restrict__ Wl, const float* __restrict__ Wr,
                        const float* __restrict__ W1) {
    int i = blockIdx.x * 256 + threadIdx.x;
    const int tot = LL * 128 * 256;
    if (i < tot) {
        int l = i / 32768;
        int r = (i >> 8) & 127;
        int c = i & 255;
        float v = (c < 128) ? Wl[l * 16384 + r * 128 + c] : Wr[l * 16384 + r * 128 + (c - 128)];
        __nv_bfloat16 h = __float2bfloat16(v);
        g_Bhi[i] = h;
        g_Blo[i] = __float2bfloat16(v - __bfloat162float(h));
    } else {
        int j = i - tot;
        if (j < 16384) {
            float v = W1[j];
            __nv_bfloat16 h = __float2bfloat16(v);
            g_W1hi[j] = h;
            g_W1lo[j] = __float2bfloat16(v - __bfloat162float(h));
        }
    }
}

// ---------------- aggregation: warp per node, cp.async->smem pipeline ----------------
// Each warp: double-buffered 8-edge batches (8 rows x 512B = 4KB per buf).
// Thread lane copies and consumes its own 16B slice (offset lane*16 of each row):
// no cross-thread smem dependency -> per-thread wait_group is sufficient.
template <int AGGR>
__global__ __launch_bounds__(256, 3)
void k_agg(const float* __restrict__ h) {
    extern __shared__ char sm[];
    const int wid = threadIdx.x >> 5, lane = threadIdx.x & 31;
    const int v = blockIdx.x * 8 + wid;
    if (v >= NN) return;
    const int beg = g_rowptr[v], end = g_rowptr[v + 1];
    const int deg = end - beg;
    const uint32_t wbase = s2u(sm) + wid * 8192;   // 2 bufs x 4096
    const char* cwbase = sm + wid * 8192;
    const int fo = lane * 4;

    float a0, a1, a2, a3;
    if (AGGR == 2) { a0 = a1 = a2 = a3 = -CUDART_INF_F; }
    else           { a0 = a1 = a2 = a3 = 0.f; }

    const int nb = (deg + 7) >> 3;

    // issue batch b into buffer (b&1): predicated cp.async (no overfetch)
    auto issue = [&](int b) {
        const uint32_t dst = wbase + (uint32_t)(b & 1) * 4096;
        const int j0 = beg + b * 8;
        #pragma unroll
        for (int i = 0; i < 8; i++) {
            int e = j0 + i;
            if (e < end) {
                int s = __ldg(&g_csrc[e]);
                cpasync16(dst + i * 512 + lane * 16, h + (size_t)s * DD + fo);
            }
        }
        asm volatile("cp.async.commit_group;" ::: "memory");
    };

    if (nb > 0) issue(0);
    for (int b = 0; b < nb; b++) {
        if (b + 1 < nb) {
            issue(b + 1);
            asm volatile("cp.async.wait_group 1;" ::: "memory");
        } else {
            asm volatile("cp.async.wait_group 0;" ::: "memory");
        }
        const char* buf = cwbase + (b & 1) * 4096;
        const int cnt = min(8, deg - b * 8);
        #pragma unroll
        for (int k = 0; k < 8; k++) {
            if (k < cnt) {
                float4 x = *(const float4*)(buf + k * 512 + lane * 16);
                if (AGGR == 2) {
                    a0 = fmaxf(a0, x.x); a1 = fmaxf(a1, x.y);
                    a2 = fmaxf(a2, x.z); a3 = fmaxf(a3, x.w);
                } else {
                    a0 += x.x; a1 += x.y; a2 += x.z; a3 += x.w;
                }
            }
        }
    }

    if (AGGR == 1) {
        float inv = (deg > 0) ? (1.0f / (float)deg) : 0.f;
        a0 *= inv; a1 *= inv; a2 *= inv; a3 *= inv;
    }
    if (AGGR == 2) {
        if (isinf(a0) && a0 < 0.f) a0 = 0.f;
        if (isinf(a1) && a1 < 0.f) a1 = 0.f;
        if (isinf(a2) && a2 < 0.f) a2 = 0.f;
        if (isinf(a3) && a3 < 0.f) a3 = 0.f;
    }
    __nv_bfloat16 h0 = __float2bfloat16(a0), h1 = __float2bfloat16(a1);
    __nv_bfloat16 h2 = __float2bfloat16(a2), h3 = __float2bfloat16(a3);
    uint32_t hi01 = ((uint32_t)__bfloat16_as_ushort(h1) << 16) | __bfloat16_as_ushort(h0);
    uint32_t hi23 = ((uint32_t)__bfloat16_as_ushort(h3) << 16) | __bfloat16_as_ushort(h2);
    uint32_t lo01 = pack2bf(a0 - __bfloat162float(h0), a1 - __bfloat162float(h1));
    uint32_t lo23 = pack2bf(a2 - __bfloat162float(h2), a3 - __bfloat162float(h3));
    *(uint2*)(g_aggHi + (size_t)v * 128 + fo) = make_uint2(hi01, hi23);
    *(uint2*)(g_aggLo + (size_t)v * 128 + fo) = make_uint2(lo01, lo23);
}

// ---------------- HMMA bf16x3 GEMM (R6 structure) ----------------
template <int NAGG>
__device__ __forceinline__ void stage_chunk(
    uint32_t sbase, char* cbase,
    const __nv_bfloat16* __restrict__ aggHi, const __nv_bfloat16* __restrict__ aggLo,
    const float* __restrict__ rootF,
    const __nv_bfloat16* __restrict__ Bhi, const __nv_bfloat16* __restrict__ Blo,
    int bstride, int n0, int c, int t) {
    const int kk = c << 5;
    if (c < NAGG) {
        #pragma unroll
        for (int i = 0; i < 4; i++) {
            int idx = i * 256 + t;
            int which = idx >> 9;
            int row = (idx >> 2) & 127;
            int q = idx & 3;
            int gr = n0 + row; if (gr >= NN) gr = NN - 1;
            const __nv_bfloat16* g = ((which == 0) ? aggHi : aggLo) + (size_t)gr * 128 + kk + q * 8;
            cpasync16(sbase + which * ABYTES + row * 80 + q * 16, g);
        }
    } else {
        int row = t >> 1, colh = t & 1;
        int gr = n0 + row; if (gr >= NN) gr = NN - 1;
        const float* src = rootF + (size_t)gr * 128 + ((c - NAGG) << 5) + colh * 16;
        float4 f0 = *(const float4*)(src);
        float4 f1 = *(const float4*)(src + 4);
        float4 f2 = *(const float4*)(src + 8);
        float4 f3 = *(const float4*)(src + 12);
        float f[16] = {f0.x, f0.y, f0.z, f0.w, f1.x, f1.y, f1.z, f1.w,
                       f2.x, f2.y, f2.z, f2.w, f3.x, f3.y, f3.z, f3.w};
        uint32_t hw[8], lw[8];
        #pragma unroll
        for (int g = 0; g < 8; g++) {
            __nv_bfloat16 h0 = __float2bfloat16(f[2 * g]);
            __nv_bfloat16 h1 = __float2bfloat16(f[2 * g + 1]);
            hw[g] = ((uint32_t)__bfloat16_as_ushort(h1) << 16) |
                    (uint32_t)__bfloat16_as_ushort(h0);
            lw[g] = pack2bf(f[2 * g] - __bfloat162float(h0),
                            f[2 * g + 1] - __bfloat162float(h1));
        }
        *(uint4*)(cbase + row * 80 + colh * 32)           = make_uint4(hw[0], hw[1], hw[2], hw[3]);
        *(uint4*)(cbase + row * 80 + colh * 32 + 16)      = make_uint4(hw[4], hw[5], hw[6], hw[7]);
        *(uint4*)(cbase + ABYTES + row * 80 + colh * 32)      = make_uint4(lw[0], lw[1], lw[2], lw[3]);
        *(uint4*)(cbase + ABYTES + row * 80 + colh * 32 + 16) = make_uint4(lw[4], lw[5], lw[6], lw[7]);
    }
    #pragma unroll
    for (int i = 0; i < 4; i++) {
        int idx = i * 256 + t;
        int which = idx >> 9;
        int row = (idx >> 2) & 127;
        int q = idx & 3;
        const __nv_bfloat16* g = ((which == 0) ? Bhi : Blo) + (size_t)row * bstride + kk + q * 8;
        cpasync16(sbase + (2 + which) * ABYTES + row * 80 + q * 16, g);
    }
    asm volatile("cp.async.commit_group;" ::: "memory");
}

template <int NAGG, int NCH>
__global__ __launch_bounds__(256, 2)
void k_tgemm(const __nv_bfloat16* __restrict__ aggHi, const __nv_bfloat16* __restrict__ aggLo,
             const float* __restrict__ rootF,
             const __nv_bfloat16* __restrict__ Bhi, const __nv_bfloat16* __restrict__ Blo,
             int bstride, const float* __restrict__ bias, float* __restrict__ outF) {
    extern __shared__ char smem[];
    float* sbias = (float*)(smem + 2 * STAGE_BYTES);

    const int t = threadIdx.x;
    const int lane = t & 31;
    const int wid = t >> 5;
    const int mw = wid & 3;
    const int nw = wid >> 2;
    const int n0 = blockIdx.x * 128;

    if (t < 128) sbias[t] = bias[t];

    const uint32_t sb0 = s2u(smem);
    const uint32_t sb1 = sb0 + STAGE_BYTES;
    const uint32_t aoff = (uint32_t)((mw * 32 + (lane & 15)) * 80 + (lane >> 4) * 16);
    const uint32_t boff = (uint32_t)((nw * 64 + ((lane >> 3) & 1) * 8 + (lane & 7)) * 80 +
                                     (lane >> 4) * 16);

    float acc[2][8][4];
    #pragma unroll
    for (int mi = 0; mi < 2; mi++)
        #pragma unroll
        for (int ni = 0; ni < 8; ni++)
            #pragma unroll
            for (int q = 0; q < 4; q++) acc[mi][ni][q] = 0.f;

    stage_chunk<NAGG>(sb0, smem, aggHi, aggLo, rootF, Bhi, Blo, bstride, n0, 0, t);

    for (int c = 0; c < NCH; c++) {
        const uint32_t cur = (c & 1) ? sb1 : sb0;
        if (c + 1 < NCH) {
            stage_chunk<NAGG>((c & 1) ? sb0 : sb1, (c & 1) ? smem : (smem + STAGE_BYTES),
                              aggHi, aggLo, rootF, Bhi, Blo, bstride, n0, c + 1, t);
            asm volatile("cp.async.wait_group 1;" ::: "memory");
        } else {
            asm volatile("cp.async.wait_group 0;" ::: "memory");
        }
        __syncthreads();

        const uint32_t uAhi = cur, uAlo = cur + ABYTES;
        const uint32_t uBhi = cur + 2 * ABYTES, uBlo = cur + 3 * ABYTES;
        #pragma unroll
        for (int ks = 0; ks < 2; ks++) {
            const uint32_t ko = ks * 32;
            uint32_t ah[2][4], al[2][4], b[4][4];
            ldsm4(ah[0][0], ah[0][1], ah[0][2], ah[0][3], uAhi + aoff + ko);
            ldsm4(ah[1][0], ah[1][1], ah[1][2], ah[1][3], uAhi + aoff + 16 * 80 + ko);
            #pragma unroll
            for (int g = 0; g < 4; g++)
                ldsm4(b[g][0], b[g][1], b[g][2], b[g][3], uBhi + boff + g * 16 * 80 + ko);
            #pragma unroll
            for (int mi = 0; mi < 2; mi++)
                #pragma unroll
                for (int g = 0; g < 4; g++) {
                    mmabf(acc[mi][2 * g],     ah[mi], b[g][0], b[g][2]);
                    mmabf(acc[mi][2 * g + 1], ah[mi], b[g][1], b[g][3]);
                }
            ldsm4(al[0][0], al[0][1], al[0][2], al[0][3], uAlo + aoff + ko);
            ldsm4(al[1][0], al[1][1], al[1][2], al[1][3], uAlo + aoff + 16 * 80 + ko);
            #pragma unroll
            for (int mi = 0; mi < 2; mi++)
                #pragma unroll
                for (int g = 0; g < 4; g++) {
                    mmabf(acc[mi][2 * g],     al[mi], b[g][0], b[g][2]);
                    mmabf(acc[mi][2 * g + 1], al[mi], b[g][1], b[g][3]);
                }
            #pragma unroll
            for (int g = 0; g < 4; g++)
                ldsm4(b[g][0], b[g][1], b[g][2], b[g][3], uBlo + boff + g * 16 * 80 + ko);
            #pragma unroll
            for (int mi = 0; mi < 2; mi++)
                #pragma unroll
                for (int g = 0; g < 4; g++) {
                    mmabf(acc[mi][2 * g],     ah[mi], b[g][0], b[g][2]);
                    mmabf(acc[mi][2 * g + 1], ah[mi], b[g][1], b[g][3]);
                }
        }
        __syncthreads();
    }

    #pragma unroll
    for (int mi = 0; mi < 2; mi++) {
        #pragma unroll
        for (int half = 0; half < 2; half++) {
            int node = n0 + mw * 32 + mi * 16 + half * 8 + (lane >> 2);
            if (node < NN) {
                #pragma unroll
                for (int ni = 0; ni < 8; ni++) {
                    int col = nw * 64 + ni * 8 + (lane & 3) * 2;
                    float v0 = fmaxf(acc[mi][ni][half * 2 + 0] + sbias[col], 0.f);
                    float v1 = fmaxf(acc[mi][ni][half * 2 + 1] + sbias[col + 1], 0.f);
                    *(float2*)(outF + (size_t)node * 128 + col) = make_float2(v0, v1);
                }
            }
        }
    }
}

// ---------------- final 128 -> 2 head ----------------
__global__ void k_head(const float* __restrict__ h, const float* __restrict__ W2,
                       const float* __restrict__ b2, float* __restrict__ out) {
    const int n = blockIdx.x;
    const int t = threadIdx.x;
    float v = h[(size_t)n * DD + t];
    float p0 = v * __ldg(&W2[t]);
    float p1 = v * __ldg(&W2[DD + t]);
    #pragma unroll
    for (int off = 16; off > 0; off >>= 1) {
        p0 += __shfl_down_sync(0xffffffff, p0, off);
        p1 += __shfl_down_sync(0xffffffff, p1, off);
    }
    __shared__ float s0[4], s1[4];
    int w = t >> 5, lane = t & 31;
    if (lane == 0) { s0[w] = p0; s1[w] = p1; }
    __syncthreads();
    if (t == 0) {
        out[n * 2 + 0] = s0[0] + s0[1] + s0[2] + s0[3] + b2[0];
        out[n * 2 + 1] = s1[0] + s1[1] + s1[2] + s1[3] + b2[1];
    }
}

// ---------------- launch ----------------
extern "C" void kernel_launch(void* const* d_in, const int* in_sizes, int n_in,
                              void* d_out, int out_size) {
    const float* x  = (const float*)d_in[0];
    const int*   ei = (const int*)  d_in[1];
    const float* Wl = (const float*)d_in[2];
    const float* bl = (const float*)d_in[3];
    const float* Wr = (const float*)d_in[4];
    const float* W1 = (const float*)d_in[5];
    const float* b1 = (const float*)d_in[6];
    const float* W2 = (const float*)d_in[7];
    const float* b2 = (const float*)d_in[8];
    float* out = (float*)d_out;

    float *h0, *h1, *hm;
    __nv_bfloat16 *aggHi, *aggLo, *bhi, *blo, *w1hi, *w1lo;
    cudaGetSymbolAddress((void**)&h0, g_h0);
    cudaGetSymbolAddress((void**)&h1, g_h1);
    cudaGetSymbolAddress((void**)&hm, g_hm);
    cudaGetSymbolAddress((void**)&aggHi, g_aggHi);
    cudaGetSymbolAddress((void**)&aggLo, g_aggLo);
    cudaGetSymbolAddress((void**)&bhi, g_Bhi);
    cudaGetSymbolAddress((void**)&blo, g_Blo);
    cudaGetSymbolAddress((void**)&w1hi, g_W1hi);
    cudaGetSymbolAddress((void**)&w1lo, g_W1lo);
    float* hb[2] = {h0, h1};

    cudaFuncSetAttribute(k_tgemm<4, 8>, cudaFuncAttributeMaxDynamicSharedMemorySize, TG_SMEM);
    cudaFuncSetAttribute(k_tgemm<0, 4>, cudaFuncAttributeMaxDynamicSharedMemorySize, TG_SMEM);
    cudaFuncSetAttribute(k_agg<0>, cudaFuncAttributeMaxDynamicSharedMemorySize, AGG_SMEM);
    cudaFuncSetAttribute(k_agg<1>, cudaFuncAttributeMaxDynamicSharedMemorySize, AGG_SMEM);
    cudaFuncSetAttribute(k_agg<2>, cudaFuncAttributeMaxDynamicSharedMemorySize, AGG_SMEM);

    // side stream: weight prep concurrent with CSR build
    static cudaStream_t s2 = nullptr;
    static cudaEvent_t eA = nullptr, eB = nullptr;
    if (s2 == nullptr) {
        cudaStreamCreateWithFlags(&s2, cudaStreamNonBlocking);
        cudaEventCreateWithFlags(&eA, cudaEventDisableTiming);
        cudaEventCreateWithFlags(&eB, cudaEventDisableTiming);
    }
    cudaEventRecord(eA, 0);
    cudaStreamWaitEvent(s2, eA, 0);
    k_wprep<<<(LL * 128 * 256 + 128 * 128 + 255) / 256, 256, 0, s2>>>(Wl, Wr, W1);
    cudaEventRecord(eB, s2);

    // CSR build (default stream)
    k_zero_deg<<<(NN + 255) / 256, 256>>>();
    k_hist<<<(EE + 255) / 256, 256>>>(ei);
    k_blocksum<<<(NN + 255) / 256, 256>>>();
    k_scanpart<<<1, 256>>>();
    k_rowptr<<<(NN + 255) / 256, 256>>>();
    k_fill<<<(EE + 255) / 256, 256>>>(ei);
    cudaStreamWaitEvent(0, eB, 0);   // weights ready before first GEMM

    static const int aggrs[LL] = {0, 1, 2, 0, 1, 2, 0, 1, 2, 0, 2, 1};
    const float* hptr = x;
    for (int i = 0; i < LL; i++) {
        switch (aggrs[i]) {
            case 0: k_agg<0><<<AGG_BLOCKS, 256, AGG_SMEM>>>(hptr); break;
            case 1: k_agg<1><<<AGG_BLOCKS, 256, AGG_SMEM>>>(hptr); break;
            default: k_agg<2><<<AGG_BLOCKS, 256, AGG_SMEM>>>(hptr); break;
        }
        float* hout = hb[i & 1];
        k_tgemm<4, 8><<<GRID_G, 256, TG_SMEM>>>(aggHi, aggLo, hptr,
                                                bhi + (size_t)i * 128 * 256,
                                                blo + (size_t)i * 128 * 256, 256,
                                                bl + (size_t)i * 128, hout);
        hptr = hout;
    }
    k_tgemm<0, 4><<<GRID_G, 256, TG_SMEM>>>(nullptr, nullptr, hptr,
                                            w1hi, w1lo, 128, b1, hm);
    k_head<<<NN, 128>>>(hm, W2, b2, out);
}

// round 12
// speedup vs baseline: 1.1559x; 1.1559x over previous
#include <cuda_runtime.h>
#include <cuda_bf16.h>
#include <math_constants.h>
#include <cstdint>

#define NN 50000
#define EE 600000
#define DD 128
#define LL 12
#define GRID_G ((NN + 127) / 128)   // 391
#define AGG_BLOCKS ((NN + 7) / 8)   // 6250

#define SROW 40
#define ABYTES (128 * SROW * 2)          // 10240 B per 128x32 bf16 array
#define STAGE_BYTES (4 * ABYTES)         // Ahi,Alo,Bhi,Blo
#define TG_SMEM (2 * STAGE_BYTES + 512)
#define MLP_SMEM (2 * STAGE_BYTES + 4096)

// ---------------- persistent device scratch ----------------
__device__ float g_h0[NN * DD];
__device__ float g_h1[NN * DD];
__device__ __nv_bfloat16 g_aggHi[NN * 128];
__device__ __nv_bfloat16 g_aggLo[NN * 128];
__device__ __nv_bfloat16 g_Bhi[LL * 128 * 256];
__device__ __nv_bfloat16 g_Blo[LL * 128 * 256];
__device__ __nv_bfloat16 g_W1hi[128 * 128];
__device__ __nv_bfloat16 g_W1lo[128 * 128];
__device__ int g_rowptr[NN + 1];
__device__ int g_woff[NN];
__device__ int g_csrc[EE];
__device__ int g_deg[NN];
__device__ int g_part[256];
__device__ int g_partscan[256];

// ---------------- helpers ----------------
__device__ __forceinline__ uint32_t s2u(const void* p) {
    uint32_t a;
    asm("{ .reg .u64 t; cvta.to.shared.u64 t, %1; cvt.u32.u64 %0, t; }" : "=r"(a) : "l"(p));
    return a;
}
__device__ __forceinline__ void ldsm4(uint32_t& r0, uint32_t& r1, uint32_t& r2, uint32_t& r3,
                                      uint32_t addr) {
    asm volatile("ldmatrix.sync.aligned.m8n8.x4.shared.b16 {%0,%1,%2,%3}, [%4];"
                 : "=r"(r0), "=r"(r1), "=r"(r2), "=r"(r3) : "r"(addr));
}
__device__ __forceinline__ void mmabf(float* c, const uint32_t* a, uint32_t b0, uint32_t b1) {
    asm volatile(
        "mma.sync.aligned.m16n8k16.row.col.f32.bf16.bf16.f32 "
        "{%0,%1,%2,%3}, {%4,%5,%6,%7}, {%8,%9}, {%0,%1,%2,%3};"
        : "+f"(c[0]), "+f"(c[1]), "+f"(c[2]), "+f"(c[3])
        : "r"(a[0]), "r"(a[1]), "r"(a[2]), "r"(a[3]), "r"(b0), "r"(b1));
}
__device__ __forceinline__ uint32_t pack2bf(float a, float b) {
    __nv_bfloat16 ha = __float2bfloat16(a), hb = __float2bfloat16(b);
    return ((uint32_t)__bfloat16_as_ushort(hb) << 16) | (uint32_t)__bfloat16_as_ushort(ha);
}
__device__ __forceinline__ void cpasync16(uint32_t dst, const void* src) {
    asm volatile("cp.async.cg.shared.global [%0], [%1], 16;" :: "r"(dst), "l"(src));
}

// ---------------- CSR build ----------------
__global__ void k_zero_deg() {
    int i = blockIdx.x * blockDim.x + threadIdx.x;
    if (i < NN) g_deg[i] = 0;
}
__global__ void k_hist(const int* __restrict__ ei) {
    int e = blockIdx.x * blockDim.x + threadIdx.x;
    if (e < EE) atomicAdd(&g_deg[ei[EE + e]], 1);
}
__global__ void k_blocksum() {
    __shared__ int sm[256];
    int t = threadIdx.x;
    int i = blockIdx.x * 256 + t;
    sm[t] = (i < NN) ? g_deg[i] : 0;
    __syncthreads();
    for (int o = 128; o > 0; o >>= 1) {
        if (t < o) sm[t] += sm[t + o];
        __syncthreads();
    }
    if (t == 0) g_part[blockIdx.x] = sm[0];
}
__global__ void k_scanpart() {
    __shared__ int sm[256];
    int t = threadIdx.x;
    int v = (t < 196) ? g_part[t] : 0;
    sm[t] = v;
    __syncthreads();
    for (int o = 1; o < 256; o <<= 1) {
        int u = (t >= o) ? sm[t - o] : 0;
        __syncthreads();
        sm[t] += u;
        __syncthreads();
    }
    g_partscan[t] = sm[t] - v;
    if (t == 0) g_rowptr[NN] = EE;
}
__global__ void k_rowptr() {
    __shared__ int sm[256];
    int t = threadIdx.x;
    int i = blockIdx.x * 256 + t;
    int v = (i < NN) ? g_deg[i] : 0;
    sm[t] = v;
    __syncthreads();
    for (int o = 1; o < 256; o <<= 1) {
        int u = (t >= o) ? sm[t - o] : 0;
        __syncthreads();
        sm[t] += u;
        __syncthreads();
    }
    if (i < NN) {
        int ex = g_partscan[blockIdx.x] + sm[t] - v;
        g_rowptr[i] = ex;
        g_woff[i] = ex;
    }
}
__global__ void k_fill(const int* __restrict__ ei) {
    int e = blockIdx.x * blockDim.x + threadIdx.x;
    if (e < EE) {
        int d = ei[EE + e];
        int p = atomicAdd(&g_woff[d], 1);
        g_csrc[p] = ei[e];
    }
}

// ---------------- weight split preprocessing ----------------
__global__ void k_wprep(const float* __restrict__ Wl, const float* __restrict__ Wr,
                        const float* __restrict__ W1) {
    int i = blockIdx.x * 256 + threadIdx.x;
    const int tot = LL * 128 * 256;
    if (i < tot) {
        int l = i / 32768;
        int r = (i >> 8) & 127;
        int c = i & 255;
        float v = (c < 128) ? Wl[l * 16384 + r * 128 + c] : Wr[l * 16384 + r * 128 + (c - 128)];
        __nv_bfloat16 h = __float2bfloat16(v);
        g_Bhi[i] = h;
        g_Blo[i] = __float2bfloat16(v - __bfloat162float(h));
    } else {
        int j = i - tot;
        if (j < 16384) {
            float v = W1[j];
            __nv_bfloat16 h = __float2bfloat16(v);
            g_W1hi[j] = h;
            g_W1lo[j] = __float2bfloat16(v - __bfloat162float(h));
        }
    }
}

// ---------------- aggregation: warp per node, 8/2/1 unroll (R6, proven) ----------------
template <int AGGR>
__global__ __launch_bounds__(256)
void k_agg(const float* __restrict__ h) {
    int wid = threadIdx.x >> 5, lane = threadIdx.x & 31;
    int v = blockIdx.x * 8 + wid;
    if (v >= NN) return;
    int beg = g_rowptr[v], end = g_rowptr[v + 1];
    float a0, a1, a2, a3;
    if (AGGR == 2) { a0 = a1 = a2 = a3 = -CUDART_INF_F; }
    else           { a0 = a1 = a2 = a3 = 0.f; }
    const int fo = lane * 4;
    int j = beg;
    for (; j + 7 < end; j += 8) {
        int s0 = __ldg(&g_csrc[j]);
        int s1 = __ldg(&g_csrc[j + 1]);
        int s2 = __ldg(&g_csrc[j + 2]);
        int s3 = __ldg(&g_csrc[j + 3]);
        int s4 = __ldg(&g_csrc[j + 4]);
        int s5 = __ldg(&g_csrc[j + 5]);
        int s6 = __ldg(&g_csrc[j + 6]);
        int s7 = __ldg(&g_csrc[j + 7]);
        float4 x0 = *(const float4*)(h + (size_t)s0 * DD + fo);
        float4 x1 = *(const float4*)(h + (size_t)s1 * DD + fo);
        float4 x2 = *(const float4*)(h + (size_t)s2 * DD + fo);
        float4 x3 = *(const float4*)(h + (size_t)s3 * DD + fo);
        float4 x4 = *(const float4*)(h + (size_t)s4 * DD + fo);
        float4 x5 = *(const float4*)(h + (size_t)s5 * DD + fo);
        float4 x6 = *(const float4*)(h + (size_t)s6 * DD + fo);
        float4 x7 = *(const float4*)(h + (size_t)s7 * DD + fo);
        if (AGGR == 2) {
            a0 = fmaxf(a0, fmaxf(fmaxf(fmaxf(x0.x, x1.x), fmaxf(x2.x, x3.x)),
                                 fmaxf(fmaxf(x4.x, x5.x), fmaxf(x6.x, x7.x))));
            a1 = fmaxf(a1, fmaxf(fmaxf(fmaxf(x0.y, x1.y), fmaxf(x2.y, x3.y)),
                                 fmaxf(fmaxf(x4.y, x5.y), fmaxf(x6.y, x7.y))));
            a2 = fmaxf(a2, fmaxf(fmaxf(fmaxf(x0.z, x1.z), fmaxf(x2.z, x3.z)),
                                 fmaxf(fmaxf(x4.z, x5.z), fmaxf(x6.z, x7.z))));
            a3 = fmaxf(a3, fmaxf(fmaxf(fmaxf(x0.w, x1.w), fmaxf(x2.w, x3.w)),
                                 fmaxf(fmaxf(x4.w, x5.w), fmaxf(x6.w, x7.w))));
        } else {
            a0 += ((x0.x + x1.x) + (x2.x + x3.x)) + ((x4.x + x5.x) + (x6.x + x7.x));
            a1 += ((x0.y + x1.y) + (x2.y + x3.y)) + ((x4.y + x5.y) + (x6.y + x7.y));
            a2 += ((x0.z + x1.z) + (x2.z + x3.z)) + ((x4.z + x5.z) + (x6.z + x7.z));
            a3 += ((x0.w + x1.w) + (x2.w + x3.w)) + ((x4.w + x5.w) + (x6.w + x7.w));
        }
    }
    for (; j + 1 < end; j += 2) {
        int s0 = __ldg(&g_csrc[j]);
        int s1 = __ldg(&g_csrc[j + 1]);
        float4 x0 = *(const float4*)(h + (size_t)s0 * DD + fo);
        float4 x1 = *(const float4*)(h + (size_t)s1 * DD + fo);
        if (AGGR == 2) {
            a0 = fmaxf(a0, fmaxf(x0.x, x1.x)); a1 = fmaxf(a1, fmaxf(x0.y, x1.y));
            a2 = fmaxf(a2, fmaxf(x0.z, x1.z)); a3 = fmaxf(a3, fmaxf(x0.w, x1.w));
        } else {
            a0 += x0.x + x1.x; a1 += x0.y + x1.y; a2 += x0.z + x1.z; a3 += x0.w + x1.w;
        }
    }
    if (j < end) {
        int s0 = __ldg(&g_csrc[j]);
        float4 x0 = *(const float4*)(h + (size_t)s0 * DD + fo);
        if (AGGR == 2) {
            a0 = fmaxf(a0, x0.x); a1 = fmaxf(a1, x0.y);
            a2 = fmaxf(a2, x0.z); a3 = fmaxf(a3, x0.w);
        } else {
            a0 += x0.x; a1 += x0.y; a2 += x0.z; a3 += x0.w;
        }
    }
    if (AGGR == 1) {
        int deg = end - beg;
        float inv = (deg > 0) ? (1.0f / (float)deg) : 0.f;
        a0 *= inv; a1 *= inv; a2 *= inv; a3 *= inv;
    }
    if (AGGR == 2) {
        if (isinf(a0) && a0 < 0.f) a0 = 0.f;
        if (isinf(a1) && a1 < 0.f) a1 = 0.f;
        if (isinf(a2) && a2 < 0.f) a2 = 0.f;
        if (isinf(a3) && a3 < 0.f) a3 = 0.f;
    }
    __nv_bfloat16 h0 = __float2bfloat16(a0), h1 = __float2bfloat16(a1);
    __nv_bfloat16 h2 = __float2bfloat16(a2), h3 = __float2bfloat16(a3);
    uint32_t hi01 = ((uint32_t)__bfloat16_as_ushort(h1) << 16) | __bfloat16_as_ushort(h0);
    uint32_t hi23 = ((uint32_t)__bfloat16_as_ushort(h3) << 16) | __bfloat16_as_ushort(h2);
    uint32_t lo01 = pack2bf(a0 - __bfloat162float(h0), a1 - __bfloat162float(h1));
    uint32_t lo23 = pack2bf(a2 - __bfloat162float(h2), a3 - __bfloat162float(h3));
    *(uint2*)(g_aggHi + (size_t)v * 128 + fo) = make_uint2(hi01, hi23);
    *(uint2*)(g_aggLo + (size_t)v * 128 + fo) = make_uint2(lo01, lo23);
}

// ---------------- GEMM staging (R6) ----------------
template <int NAGG>
__device__ __forceinline__ void stage_chunk(
    uint32_t sbase, char* cbase,
    const __nv_bfloat16* __restrict__ aggHi, const __nv_bfloat16* __restrict__ aggLo,
    const float* __restrict__ rootF,
    const __nv_bfloat16* __restrict__ Bhi, const __nv_bfloat16* __restrict__ Blo,
    int bstride, int n0, int c, int t) {
    const int kk = c << 5;
    if (c < NAGG) {
        #pragma unroll
        for (int i = 0; i < 4; i++) {
            int idx = i * 256 + t;
            int which = idx >> 9;
            int row = (idx >> 2) & 127;
            int q = idx & 3;
            int gr = n0 + row; if (gr >= NN) gr = NN - 1;
            const __nv_bfloat16* g = ((which == 0) ? aggHi : aggLo) + (size_t)gr * 128 + kk + q * 8;
            cpasync16(sbase + which * ABYTES + row * 80 + q * 16, g);
        }
    } else {
        int row = t >> 1, colh = t & 1;
        int gr = n0 + row; if (gr >= NN) gr = NN - 1;
        const float* src = rootF + (size_t)gr * 128 + ((c - NAGG) << 5) + colh * 16;
        float4 f0 = *(const float4*)(src);
        float4 f1 = *(const float4*)(src + 4);
        float4 f2 = *(const float4*)(src + 8);
        float4 f3 = *(const float4*)(src + 12);
        float f[16] = {f0.x, f0.y, f0.z, f0.w, f1.x, f1.y, f1.z, f1.w,
                       f2.x, f2.y, f2.z, f2.w, f3.x, f3.y, f3.z, f3.w};
        uint32_t hw[8], lw[8];
        #pragma unroll
        for (int g = 0; g < 8; g++) {
            __nv_bfloat16 h0 = __float2bfloat16(f[2 * g]);
            __nv_bfloat16 h1 = __float2bfloat16(f[2 * g + 1]);
            hw[g] = ((uint32_t)__bfloat16_as_ushort(h1) << 16) |
                    (uint32_t)__bfloat16_as_ushort(h0);
            lw[g] = pack2bf(f[2 * g] - __bfloat162float(h0),
                            f[2 * g + 1] - __bfloat162float(h1));
        }
        *(uint4*)(cbase + row * 80 + colh * 32)           = make_uint4(hw[0], hw[1], hw[2], hw[3]);
        *(uint4*)(cbase + row * 80 + colh * 32 + 16)      = make_uint4(hw[4], hw[5], hw[6], hw[7]);
        *(uint4*)(cbase + ABYTES + row * 80 + colh * 32)      = make_uint4(lw[0], lw[1], lw[2], lw[3]);
        *(uint4*)(cbase + ABYTES + row * 80 + colh * 32 + 16) = make_uint4(lw[4], lw[5], lw[6], lw[7]);
    }
    #pragma unroll
    for (int i = 0; i < 4; i++) {
        int idx = i * 256 + t;
        int which = idx >> 9;
        int row = (idx >> 2) & 127;
        int q = idx & 3;
        const __nv_bfloat16* g = ((which == 0) ? Bhi : Blo) + (size_t)row * bstride + kk + q * 8;
        cpasync16(sbase + (2 + which) * ABYTES + row * 80 + q * 16, g);
    }
    asm volatile("cp.async.commit_group;" ::: "memory");
}

__device__ __forceinline__ void chunk_mma(uint32_t cur, uint32_t aoff, uint32_t boff,
                                          float acc[2][8][4]) {
    const uint32_t uAhi = cur, uAlo = cur + ABYTES;
    const uint32_t uBhi = cur + 2 * ABYTES, uBlo = cur + 3 * ABYTES;
    #pragma unroll
    for (int ks = 0; ks < 2; ks++) {
        const uint32_t ko = ks * 32;
        uint32_t ah[2][4], al[2][4], b[4][4];
        ldsm4(ah[0][0], ah[0][1], ah[0][2], ah[0][3], uAhi + aoff + ko);
        ldsm4(ah[1][0], ah[1][1], ah[1][2], ah[1][3], uAhi + aoff + 16 * 80 + ko);
        #pragma unroll
        for (int g = 0; g < 4; g++)
            ldsm4(b[g][0], b[g][1], b[g][2], b[g][3], uBhi + boff + g * 16 * 80 + ko);
        #pragma unroll
        for (int mi = 0; mi < 2; mi++)
            #pragma unroll
            for (int g = 0; g < 4; g++) {
                mmabf(acc[mi][2 * g],     ah[mi], b[g][0], b[g][2]);
                mmabf(acc[mi][2 * g + 1], ah[mi], b[g][1], b[g][3]);
            }
        ldsm4(al[0][0], al[0][1], al[0][2], al[0][3], uAlo + aoff + ko);
        ldsm4(al[1][0], al[1][1], al[1][2], al[1][3], uAlo + aoff + 16 * 80 + ko);
        #pragma unroll
        for (int mi = 0; mi < 2; mi++)
            #pragma unroll
            for (int g = 0; g < 4; g++) {
                mmabf(acc[mi][2 * g],     al[mi], b[g][0], b[g][2]);
                mmabf(acc[mi][2 * g + 1], al[mi], b[g][1], b[g][3]);
            }
        #pragma unroll
        for (int g = 0; g < 4; g++)
            ldsm4(b[g][0], b[g][1], b[g][2], b[g][3], uBlo + boff + g * 16 * 80 + ko);
        #pragma unroll
        for (int mi = 0; mi < 2; mi++)
            #pragma unroll
            for (int g = 0; g < 4; g++) {
                mmabf(acc[mi][2 * g],     ah[mi], b[g][0], b[g][2]);
                mmabf(acc[mi][2 * g + 1], ah[mi], b[g][1], b[g][3]);
            }
    }
}

// ---------------- per-layer GEMM (R6 exact) ----------------
__global__ __launch_bounds__(256, 2)
void k_tgemm(const __nv_bfloat16* __restrict__ aggHi, const __nv_bfloat16* __restrict__ aggLo,
             const float* __restrict__ rootF,
             const __nv_bfloat16* __restrict__ Bhi, const __nv_bfloat16* __restrict__ Blo,
             const float* __restrict__ bias, float* __restrict__ outF) {
    extern __shared__ char smem[];
    float* sbias = (float*)(smem + 2 * STAGE_BYTES);

    const int t = threadIdx.x;
    const int lane = t & 31;
    const int wid = t >> 5;
    const int mw = wid & 3;
    const int nw = wid >> 2;
    const int n0 = blockIdx.x * 128;

    if (t < 128) sbias[t] = bias[t];

    const uint32_t sb0 = s2u(smem);
    const uint32_t sb1 = sb0 + STAGE_BYTES;
    const uint32_t aoff = (uint32_t)((mw * 32 + (lane & 15)) * 80 + (lane >> 4) * 16);
    const uint32_t boff = (uint32_t)((nw * 64 + ((lane >> 3) & 1) * 8 + (lane & 7)) * 80 +
                                     (lane >> 4) * 16);

    float acc[2][8][4];
    #pragma unroll
    for (int mi = 0; mi < 2; mi++)
        #pragma unroll
        for (int ni = 0; ni < 8; ni++)
            #pragma unroll
            for (int q = 0; q < 4; q++) acc[mi][ni][q] = 0.f;

    stage_chunk<4>(sb0, smem, aggHi, aggLo, rootF, Bhi, Blo, 256, n0, 0, t);

    for (int c = 0; c < 8; c++) {
        const uint32_t cur = (c & 1) ? sb1 : sb0;
        if (c + 1 < 8) {
            stage_chunk<4>((c & 1) ? sb0 : sb1, (c & 1) ? smem : (smem + STAGE_BYTES),
                           aggHi, aggLo, rootF, Bhi, Blo, 256, n0, c + 1, t);
            asm volatile("cp.async.wait_group 1;" ::: "memory");
        } else {
            asm volatile("cp.async.wait_group 0;" ::: "memory");
        }
        __syncthreads();
        chunk_mma(cur, aoff, boff, acc);
        __syncthreads();
    }

    #pragma unroll
    for (int mi = 0; mi < 2; mi++) {
        #pragma unroll
        for (int half = 0; half < 2; half++) {
            int node = n0 + mw * 32 + mi * 16 + half * 8 + (lane >> 2);
            if (node < NN) {
                #pragma unroll
                for (int ni = 0; ni < 8; ni++) {
                    int col = nw * 64 + ni * 8 + (lane & 3) * 2;
                    float v0 = fmaxf(acc[mi][ni][half * 2 + 0] + sbias[col], 0.f);
                    float v1 = fmaxf(acc[mi][ni][half * 2 + 1] + sbias[col + 1], 0.f);
                    *(float2*)(outF + (size_t)node * 128 + col) = make_float2(v0, v1);
                }
            }
        }
    }
}

// ---------------- final MLP GEMM with fused 128->2 head ----------------
__global__ __launch_bounds__(256, 2)
void k_mlp(const float* __restrict__ rootF,
           const __nv_bfloat16* __restrict__ Bhi, const __nv_bfloat16* __restrict__ Blo,
           const float* __restrict__ b1, const float* __restrict__ W2,
           const float* __restrict__ b2, float* __restrict__ out) {
    extern __shared__ char smem[];
    float* sbias = (float*)(smem + 2 * STAGE_BYTES);
    float* sW2   = sbias + 128;   // 256 floats
    float* shead = sW2 + 256;     // 256 floats

    const int t = threadIdx.x;
    const int lane = t & 31;
    const int wid = t >> 5;
    const int mw = wid & 3;
    const int nw = wid >> 2;
    const int n0 = blockIdx.x * 128;

    if (t < 128) {
        sbias[t] = b1[t];
        sW2[t] = W2[t];
        sW2[128 + t] = W2[128 + t];
        shead[2 * t] = 0.f;
        shead[2 * t + 1] = 0.f;
    }

    const uint32_t sb0 = s2u(smem);
    const uint32_t sb1 = sb0 + STAGE_BYTES;
    const uint32_t aoff = (uint32_t)((mw * 32 + (lane & 15)) * 80 + (lane >> 4) * 16);
    const uint32_t boff = (uint32_t)((nw * 64 + ((lane >> 3) & 1) * 8 + (lane & 7)) * 80 +
                                     (lane >> 4) * 16);

    float acc[2][8][4];
    #pragma unroll
    for (int mi = 0; mi < 2; mi++)
        #pragma unroll
        for (int ni = 0; ni < 8; ni++)
            #pragma unroll
            for (int q = 0; q < 4; q++) acc[mi][ni][q] = 0.f;

    stage_chunk<0>(sb0, smem, nullptr, nullptr, rootF, Bhi, Blo, 128, n0, 0, t);

    for (int c = 0; c < 4; c++) {
        const uint32_t cur = (c & 1) ? sb1 : sb0;
        if (c + 1 < 4) {
            stage_chunk<0>((c & 1) ? sb0 : sb1, (c & 1) ? smem : (smem + STAGE_BYTES),
                           nullptr, nullptr, rootF, Bhi, Blo, 128, n0, c + 1, t);
            asm volatile("cp.async.wait_group 1;" ::: "memory");
        } else {
            asm volatile("cp.async.wait_group 0;" ::: "memory");
        }
        __syncthreads();
        chunk_mma(cur, aoff, boff, acc);
        __syncthreads();
    }

    // fused head: v = relu(acc + b1); partial = v . W2row; shared-atomic reduce
    #pragma unroll
    for (int mi = 0; mi < 2; mi++) {
        #pragma unroll
        for (int half = 0; half < 2; half++) {
            int nl = mw * 32 + mi * 16 + half * 8 + (lane >> 2);   // 0..127
            float p0 = 0.f, p1 = 0.f;
            #pragma unroll
            for (int ni = 0; ni < 8; ni++) {
                int col = nw * 64 + ni * 8 + (lane & 3) * 2;
                float v0 = fmaxf(acc[mi][ni][half * 2 + 0] + sbias[col], 0.f);
                float v1 = fmaxf(acc[mi][ni][half * 2 + 1] + sbias[col + 1], 0.f);
                p0 += v0 * sW2[col] + v1 * sW2[col + 1];
                p1 += v0 * sW2[128 + col] + v1 * sW2[128 + col + 1];
            }
            atomicAdd(&shead[2 * nl], p0);
            atomicAdd(&shead[2 * nl + 1], p1);
        }
    }
    __syncthreads();
    if (t < 128) {
        int n = n0 + t;
        if (n < NN) {
            out[n * 2 + 0] = shead[2 * t] + b2[0];
            out[n * 2 + 1] = shead[2 * t + 1] + b2[1];
        }
    }
}

// ---------------- launch ----------------
extern "C" void kernel_launch(void* const* d_in, const int* in_sizes, int n_in,
                              void* d_out, int out_size) {
    const float* x  = (const float*)d_in[0];
    const int*   ei = (const int*)  d_in[1];
    const float* Wl = (const float*)d_in[2];
    const float* bl = (const float*)d_in[3];
    const float* Wr = (const float*)d_in[4];
    const float* W1 = (const float*)d_in[5];
    const float* b1 = (const float*)d_in[6];
    const float* W2 = (const float*)d_in[7];
    const float* b2 = (const float*)d_in[8];
    float* out = (float*)d_out;

    float *h0, *h1;
    __nv_bfloat16 *aggHi, *aggLo, *bhi, *blo, *w1hi, *w1lo;
    cudaGetSymbolAddress((void**)&h0, g_h0);
    cudaGetSymbolAddress((void**)&h1, g_h1);
    cudaGetSymbolAddress((void**)&aggHi, g_aggHi);
    cudaGetSymbolAddress((void**)&aggLo, g_aggLo);
    cudaGetSymbolAddress((void**)&bhi, g_Bhi);
    cudaGetSymbolAddress((void**)&blo, g_Blo);
    cudaGetSymbolAddress((void**)&w1hi, g_W1hi);
    cudaGetSymbolAddress((void**)&w1lo, g_W1lo);
    float* hb[2] = {h0, h1};

    cudaFuncSetAttribute(k_tgemm, cudaFuncAttributeMaxDynamicSharedMemorySize, TG_SMEM);
    cudaFuncSetAttribute(k_mlp, cudaFuncAttributeMaxDynamicSharedMemorySize, MLP_SMEM);

    // side stream: weight prep concurrent with CSR build
    static cudaStream_t s2 = nullptr;
    static cudaEvent_t eA = nullptr, eB = nullptr;
    if (s2 == nullptr) {
        cudaStreamCreateWithFlags(&s2, cudaStreamNonBlocking);
        cudaEventCreateWithFlags(&eA, cudaEventDisableTiming);
        cudaEventCreateWithFlags(&eB, cudaEventDisableTiming);
    }
    cudaEventRecord(eA, 0);
    cudaStreamWaitEvent(s2, eA, 0);
    k_wprep<<<(LL * 128 * 256 + 128 * 128 + 255) / 256, 256, 0, s2>>>(Wl, Wr, W1);
    cudaEventRecord(eB, s2);

    // CSR build (default stream)
    k_zero_deg<<<(NN + 255) / 256, 256>>>();
    k_hist<<<(EE + 255) / 256, 256>>>(ei);
    k_blocksum<<<(NN + 255) / 256, 256>>>();
    k_scanpart<<<1, 256>>>();
    k_rowptr<<<(NN + 255) / 256, 256>>>();
    k_fill<<<(EE + 255) / 256, 256>>>(ei);
    cudaStreamWaitEvent(0, eB, 0);   // weights ready before first GEMM

    static const int aggrs[LL] = {0, 1, 2, 0, 1, 2, 0, 1, 2, 0, 2, 1};
    const float* hptr = x;
    for (int i = 0; i < LL; i++) {
        switch (aggrs[i]) {
            case 0: k_agg<0><<<AGG_BLOCKS, 256>>>(hptr); break;
            case 1: k_agg<1><<<AGG_BLOCKS, 256>>>(hptr); break;
            default: k_agg<2><<<AGG_BLOCKS, 256>>>(hptr); break;
        }
        float* hout = hb[i & 1];
        k_tgemm<<<GRID_G, 256, TG_SMEM>>>(aggHi, aggLo, hptr,
                                          bhi + (size_t)i * 128 * 256,
                                          blo + (size_t)i * 128 * 256,
                                          bl + (size_t)i * 128, hout);
        hptr = hout;
    }
    k_mlp<<<GRID_G, 256, MLP_SMEM>>>(hptr, w1hi, w1lo, b1, W2, b2, out);
}

// round 13
// speedup vs baseline: 1.1726x; 1.0144x over previous
#include <cuda_runtime.h>
#include <cuda_bf16.h>
#include <math_constants.h>
#include <cstdint>

#define NN 50000
#define EE 600000
#define DD 128
#define LL 12
#define GRID_G ((NN + 127) / 128)   // 391
#define AGG_BLOCKS ((NN + 7) / 8)   // 6250

#define SROW 40
#define ABYTES (128 * SROW * 2)          // 10240 B per 128x32 bf16 array
#define STAGE_BYTES (4 * ABYTES)         // Ahi,Alo,Bhi,Blo
#define TG_SMEM (2 * STAGE_BYTES + 512)
#define MLP_SMEM (2 * STAGE_BYTES + 4096)

// ---------------- persistent device scratch ----------------
__device__ float g_h0[NN * DD];
__device__ float g_h1[NN * DD];
__device__ __nv_bfloat16 g_aggHi[NN * 128];
__device__ __nv_bfloat16 g_aggLo[NN * 128];
__device__ __nv_bfloat16 g_Bhi[LL * 128 * 256];
__device__ __nv_bfloat16 g_Blo[LL * 128 * 256];
__device__ __nv_bfloat16 g_W1hi[128 * 128];
__device__ __nv_bfloat16 g_W1lo[128 * 128];
__device__ int g_rowptr[NN + 1];
__device__ int g_woff[NN];
__device__ int g_csrc[EE];
__device__ int g_deg[NN];
__device__ int g_part[256];
__device__ int g_partscan[256];

// ---------------- helpers ----------------
__device__ __forceinline__ uint32_t s2u(const void* p) {
    uint32_t a;
    asm("{ .reg .u64 t; cvta.to.shared.u64 t, %1; cvt.u32.u64 %0, t; }" : "=r"(a) : "l"(p));
    return a;
}
__device__ __forceinline__ void ldsm4(uint32_t& r0, uint32_t& r1, uint32_t& r2, uint32_t& r3,
                                      uint32_t addr) {
    asm volatile("ldmatrix.sync.aligned.m8n8.x4.shared.b16 {%0,%1,%2,%3}, [%4];"
                 : "=r"(r0), "=r"(r1), "=r"(r2), "=r"(r3) : "r"(addr));
}
__device__ __forceinline__ void mmabf(float* c, const uint32_t* a, uint32_t b0, uint32_t b1) {
    asm volatile(
        "mma.sync.aligned.m16n8k16.row.col.f32.bf16.bf16.f32 "
        "{%0,%1,%2,%3}, {%4,%5,%6,%7}, {%8,%9}, {%0,%1,%2,%3};"
        : "+f"(c[0]), "+f"(c[1]), "+f"(c[2]), "+f"(c[3])
        : "r"(a[0]), "r"(a[1]), "r"(a[2]), "r"(a[3]), "r"(b0), "r"(b1));
}
__device__ __forceinline__ uint32_t pack2bf(float a, float b) {
    __nv_bfloat16 ha = __float2bfloat16(a), hb = __float2bfloat16(b);
    return ((uint32_t)__bfloat16_as_ushort(hb) << 16) | (uint32_t)__bfloat16_as_ushort(ha);
}
__device__ __forceinline__ void cpasync16(uint32_t dst, const void* src) {
    asm volatile("cp.async.cg.shared.global [%0], [%1], 16;" :: "r"(dst), "l"(src));
}

// ---------------- CSR build ----------------
__global__ void k_zero_deg() {
    int i = blockIdx.x * blockDim.x + threadIdx.x;
    if (i < NN) g_deg[i] = 0;
}
__global__ void k_hist(const int* __restrict__ ei) {
    int e = blockIdx.x * blockDim.x + threadIdx.x;
    if (e < EE) atomicAdd(&g_deg[ei[EE + e]], 1);
}
__global__ void k_blocksum() {
    __shared__ int sm[256];
    int t = threadIdx.x;
    int i = blockIdx.x * 256 + t;
    sm[t] = (i < NN) ? g_deg[i] : 0;
    __syncthreads();
    for (int o = 128; o > 0; o >>= 1) {
        if (t < o) sm[t] += sm[t + o];
        __syncthreads();
    }
    if (t == 0) g_part[blockIdx.x] = sm[0];
}
__global__ void k_scanpart() {
    __shared__ int sm[256];
    int t = threadIdx.x;
    int v = (t < 196) ? g_part[t] : 0;
    sm[t] = v;
    __syncthreads();
    for (int o = 1; o < 256; o <<= 1) {
        int u = (t >= o) ? sm[t - o] : 0;
        __syncthreads();
        sm[t] += u;
        __syncthreads();
    }
    g_partscan[t] = sm[t] - v;
    if (t == 0) g_rowptr[NN] = EE;
}
__global__ void k_rowptr() {
    __shared__ int sm[256];
    int t = threadIdx.x;
    int i = blockIdx.x * 256 + t;
    int v = (i < NN) ? g_deg[i] : 0;
    sm[t] = v;
    __syncthreads();
    for (int o = 1; o < 256; o <<= 1) {
        int u = (t >= o) ? sm[t - o] : 0;
        __syncthreads();
        sm[t] += u;
        __syncthreads();
    }
    if (i < NN) {
        int ex = g_partscan[blockIdx.x] + sm[t] - v;
        g_rowptr[i] = ex;
        g_woff[i] = ex;
    }
}
__global__ void k_fill(const int* __restrict__ ei) {
    int e = blockIdx.x * blockDim.x + threadIdx.x;
    if (e < EE) {
        int d = ei[EE + e];
        int p = atomicAdd(&g_woff[d], 1);
        g_csrc[p] = ei[e];
    }
}

// ---------------- weight split preprocessing ----------------
__global__ void k_wprep(const float* __restrict__ Wl, const float* __restrict__ Wr,
                        const float* __restrict__ W1) {
    int i = blockIdx.x * 256 + threadIdx.x;
    const int tot = LL * 128 * 256;
    if (i < tot) {
        int l = i / 32768;
        int r = (i >> 8) & 127;
        int c = i & 255;
        float v = (c < 128) ? Wl[l * 16384 + r * 128 + c] : Wr[l * 16384 + r * 128 + (c - 128)];
        __nv_bfloat16 h = __float2bfloat16(v);
        g_Bhi[i] = h;
        g_Blo[i] = __float2bfloat16(v - __bfloat162float(h));
    } else {
        int j = i - tot;
        if (j < 16384) {
            float v = W1[j];
            __nv_bfloat16 h = __float2bfloat16(v);
            g_W1hi[j] = h;
            g_W1lo[j] = __float2bfloat16(v - __bfloat162float(h));
        }
    }
}

// ---------------- aggregation: warp per node, 8/4/2/1 unroll ----------------
template <int AGGR>
__global__ __launch_bounds__(256)
void k_agg(const float* __restrict__ h) {
    int wid = threadIdx.x >> 5, lane = threadIdx.x & 31;
    int v = blockIdx.x * 8 + wid;
    if (v >= NN) return;
    int beg = g_rowptr[v], end = g_rowptr[v + 1];
    float a0, a1, a2, a3;
    if (AGGR == 2) { a0 = a1 = a2 = a3 = -CUDART_INF_F; }
    else           { a0 = a1 = a2 = a3 = 0.f; }
    const int fo = lane * 4;
    int j = beg;
    for (; j + 7 < end; j += 8) {
        int s0 = __ldg(&g_csrc[j]);
        int s1 = __ldg(&g_csrc[j + 1]);
        int s2 = __ldg(&g_csrc[j + 2]);
        int s3 = __ldg(&g_csrc[j + 3]);
        int s4 = __ldg(&g_csrc[j + 4]);
        int s5 = __ldg(&g_csrc[j + 5]);
        int s6 = __ldg(&g_csrc[j + 6]);
        int s7 = __ldg(&g_csrc[j + 7]);
        float4 x0 = *(const float4*)(h + (size_t)s0 * DD + fo);
        float4 x1 = *(const float4*)(h + (size_t)s1 * DD + fo);
        float4 x2 = *(const float4*)(h + (size_t)s2 * DD + fo);
        float4 x3 = *(const float4*)(h + (size_t)s3 * DD + fo);
        float4 x4 = *(const float4*)(h + (size_t)s4 * DD + fo);
        float4 x5 = *(const float4*)(h + (size_t)s5 * DD + fo);
        float4 x6 = *(const float4*)(h + (size_t)s6 * DD + fo);
        float4 x7 = *(const float4*)(h + (size_t)s7 * DD + fo);
        if (AGGR == 2) {
            a0 = fmaxf(a0, fmaxf(fmaxf(fmaxf(x0.x, x1.x), fmaxf(x2.x, x3.x)),
                                 fmaxf(fmaxf(x4.x, x5.x), fmaxf(x6.x, x7.x))));
            a1 = fmaxf(a1, fmaxf(fmaxf(fmaxf(x0.y, x1.y), fmaxf(x2.y, x3.y)),
                                 fmaxf(fmaxf(x4.y, x5.y), fmaxf(x6.y, x7.y))));
            a2 = fmaxf(a2, fmaxf(fmaxf(fmaxf(x0.z, x1.z), fmaxf(x2.z, x3.z)),
                                 fmaxf(fmaxf(x4.z, x5.z), fmaxf(x6.z, x7.z))));
            a3 = fmaxf(a3, fmaxf(fmaxf(fmaxf(x0.w, x1.w), fmaxf(x2.w, x3.w)),
                                 fmaxf(fmaxf(x4.w, x5.w), fmaxf(x6.w, x7.w))));
        } else {
            a0 += ((x0.x + x1.x) + (x2.x + x3.x)) + ((x4.x + x5.x) + (x6.x + x7.x));
            a1 += ((x0.y + x1.y) + (x2.y + x3.y)) + ((x4.y + x5.y) + (x6.y + x7.y));
            a2 += ((x0.z + x1.z) + (x2.z + x3.z)) + ((x4.z + x5.z) + (x6.z + x7.z));
            a3 += ((x0.w + x1.w) + (x2.w + x3.w)) + ((x4.w + x5.w) + (x6.w + x7.w));
        }
    }
    if (j + 3 < end) {
        int s0 = __ldg(&g_csrc[j]);
        int s1 = __ldg(&g_csrc[j + 1]);
        int s2 = __ldg(&g_csrc[j + 2]);
        int s3 = __ldg(&g_csrc[j + 3]);
        float4 x0 = *(const float4*)(h + (size_t)s0 * DD + fo);
        float4 x1 = *(const float4*)(h + (size_t)s1 * DD + fo);
        float4 x2 = *(const float4*)(h + (size_t)s2 * DD + fo);
        float4 x3 = *(const float4*)(h + (size_t)s3 * DD + fo);
        if (AGGR == 2) {
            a0 = fmaxf(a0, fmaxf(fmaxf(x0.x, x1.x), fmaxf(x2.x, x3.x)));
            a1 = fmaxf(a1, fmaxf(fmaxf(x0.y, x1.y), fmaxf(x2.y, x3.y)));
            a2 = fmaxf(a2, fmaxf(fmaxf(x0.z, x1.z), fmaxf(x2.z, x3.z)));
            a3 = fmaxf(a3, fmaxf(fmaxf(x0.w, x1.w), fmaxf(x2.w, x3.w)));
        } else {
            a0 += (x0.x + x1.x) + (x2.x + x3.x);
            a1 += (x0.y + x1.y) + (x2.y + x3.y);
            a2 += (x0.z + x1.z) + (x2.z + x3.z);
            a3 += (x0.w + x1.w) + (x2.w + x3.w);
        }
        j += 4;
    }
    if (j + 1 < end) {
        int s0 = __ldg(&g_csrc[j]);
        int s1 = __ldg(&g_csrc[j + 1]);
        float4 x0 = *(const float4*)(h + (size_t)s0 * DD + fo);
        float4 x1 = *(const float4*)(h + (size_t)s1 * DD + fo);
        if (AGGR == 2) {
            a0 = fmaxf(a0, fmaxf(x0.x, x1.x)); a1 = fmaxf(a1, fmaxf(x0.y, x1.y));
            a2 = fmaxf(a2, fmaxf(x0.z, x1.z)); a3 = fmaxf(a3, fmaxf(x0.w, x1.w));
        } else {
            a0 += x0.x + x1.x; a1 += x0.y + x1.y; a2 += x0.z + x1.z; a3 += x0.w + x1.w;
        }
        j += 2;
    }
    if (j < end) {
        int s0 = __ldg(&g_csrc[j]);
        float4 x0 = *(const float4*)(h + (size_t)s0 * DD + fo);
        if (AGGR == 2) {
            a0 = fmaxf(a0, x0.x); a1 = fmaxf(a1, x0.y);
            a2 = fmaxf(a2, x0.z); a3 = fmaxf(a3, x0.w);
        } else {
            a0 += x0.x; a1 += x0.y; a2 += x0.z; a3 += x0.w;
        }
    }
    if (AGGR == 1) {
        int deg = end - beg;
        float inv = (deg > 0) ? (1.0f / (float)deg) : 0.f;
        a0 *= inv; a1 *= inv; a2 *= inv; a3 *= inv;
    }
    if (AGGR == 2) {
        if (isinf(a0) && a0 < 0.f) a0 = 0.f;
        if (isinf(a1) && a1 < 0.f) a1 = 0.f;
        if (isinf(a2) && a2 < 0.f) a2 = 0.f;
        if (isinf(a3) && a3 < 0.f) a3 = 0.f;
    }
    __nv_bfloat16 h0 = __float2bfloat16(a0), h1 = __float2bfloat16(a1);
    __nv_bfloat16 h2 = __float2bfloat16(a2), h3 = __float2bfloat16(a3);
    uint32_t hi01 = ((uint32_t)__bfloat16_as_ushort(h1) << 16) | __bfloat16_as_ushort(h0);
    uint32_t hi23 = ((uint32_t)__bfloat16_as_ushort(h3) << 16) | __bfloat16_as_ushort(h2);
    uint32_t lo01 = pack2bf(a0 - __bfloat162float(h0), a1 - __bfloat162float(h1));
    uint32_t lo23 = pack2bf(a2 - __bfloat162float(h2), a3 - __bfloat162float(h3));
    *(uint2*)(g_aggHi + (size_t)v * 128 + fo) = make_uint2(hi01, hi23);
    *(uint2*)(g_aggLo + (size_t)v * 128 + fo) = make_uint2(lo01, lo23);
}

// ---------------- GEMM staging (R12) ----------------
template <int NAGG>
__device__ __forceinline__ void stage_chunk(
    uint32_t sbase, char* cbase,
    const __nv_bfloat16* __restrict__ aggHi, const __nv_bfloat16* __restrict__ aggLo,
    const float* __restrict__ rootF,
    const __nv_bfloat16* __restrict__ Bhi, const __nv_bfloat16* __restrict__ Blo,
    int bstride, int n0, int c, int t) {
    const int kk = c << 5;
    if (c < NAGG) {
        #pragma unroll
        for (int i = 0; i < 4; i++) {
            int idx = i * 256 + t;
            int which = idx >> 9;
            int row = (idx >> 2) & 127;
            int q = idx & 3;
            int gr = n0 + row; if (gr >= NN) gr = NN - 1;
            const __nv_bfloat16* g = ((which == 0) ? aggHi : aggLo) + (size_t)gr * 128 + kk + q * 8;
            cpasync16(sbase + which * ABYTES + row * 80 + q * 16, g);
        }
    } else {
        int row = t >> 1, colh = t & 1;
        int gr = n0 + row; if (gr >= NN) gr = NN - 1;
        const float* src = rootF + (size_t)gr * 128 + ((c - NAGG) << 5) + colh * 16;
        float4 f0 = *(const float4*)(src);
        float4 f1 = *(const float4*)(src + 4);
        float4 f2 = *(const float4*)(src + 8);
        float4 f3 = *(const float4*)(src + 12);
        float f[16] = {f0.x, f0.y, f0.z, f0.w, f1.x, f1.y, f1.z, f1.w,
                       f2.x, f2.y, f2.z, f2.w, f3.x, f3.y, f3.z, f3.w};
        uint32_t hw[8], lw[8];
        #pragma unroll
        for (int g = 0; g < 8; g++) {
            __nv_bfloat16 h0 = __float2bfloat16(f[2 * g]);
            __nv_bfloat16 h1 = __float2bfloat16(f[2 * g + 1]);
            hw[g] = ((uint32_t)__bfloat16_as_ushort(h1) << 16) |
                    (uint32_t)__bfloat16_as_ushort(h0);
            lw[g] = pack2bf(f[2 * g] - __bfloat162float(h0),
                            f[2 * g + 1] - __bfloat162float(h1));
        }
        *(uint4*)(cbase + row * 80 + colh * 32)           = make_uint4(hw[0], hw[1], hw[2], hw[3]);
        *(uint4*)(cbase + row * 80 + colh * 32 + 16)      = make_uint4(hw[4], hw[5], hw[6], hw[7]);
        *(uint4*)(cbase + ABYTES + row * 80 + colh * 32)      = make_uint4(lw[0], lw[1], lw[2], lw[3]);
        *(uint4*)(cbase + ABYTES + row * 80 + colh * 32 + 16) = make_uint4(lw[4], lw[5], lw[6], lw[7]);
    }
    #pragma unroll
    for (int i = 0; i < 4; i++) {
        int idx = i * 256 + t;
        int which = idx >> 9;
        int row = (idx >> 2) & 127;
        int q = idx & 3;
        const __nv_bfloat16* g = ((which == 0) ? Bhi : Blo) + (size_t)row * bstride + kk + q * 8;
        cpasync16(sbase + (2 + which) * ABYTES + row * 80 + q * 16, g);
    }
    asm volatile("cp.async.commit_group;" ::: "memory");
}

__device__ __forceinline__ void chunk_mma(uint32_t cur, uint32_t aoff, uint32_t boff,
                                          float acc[2][8][4]) {
    const uint32_t uAhi = cur, uAlo = cur + ABYTES;
    const uint32_t uBhi = cur + 2 * ABYTES, uBlo = cur + 3 * ABYTES;
    #pragma unroll
    for (int ks = 0; ks < 2; ks++) {
        const uint32_t ko = ks * 32;
        uint32_t ah[2][4], al[2][4], b[4][4];
        ldsm4(ah[0][0], ah[0][1], ah[0][2], ah[0][3], uAhi + aoff + ko);
        ldsm4(ah[1][0], ah[1][1], ah[1][2], ah[1][3], uAhi + aoff + 16 * 80 + ko);
        #pragma unroll
        for (int g = 0; g < 4; g++)
            ldsm4(b[g][0], b[g][1], b[g][2], b[g][3], uBhi + boff + g * 16 * 80 + ko);
        #pragma unroll
        for (int mi = 0; mi < 2; mi++)
            #pragma unroll
            for (int g = 0; g < 4; g++) {
                mmabf(acc[mi][2 * g],     ah[mi], b[g][0], b[g][2]);
                mmabf(acc[mi][2 * g + 1], ah[mi], b[g][1], b[g][3]);
            }
        ldsm4(al[0][0], al[0][1], al[0][2], al[0][3], uAlo + aoff + ko);
        ldsm4(al[1][0], al[1][1], al[1][2], al[1][3], uAlo + aoff + 16 * 80 + ko);
        #pragma unroll
        for (int mi = 0; mi < 2; mi++)
            #pragma unroll
            for (int g = 0; g < 4; g++) {
                mmabf(acc[mi][2 * g],     al[mi], b[g][0], b[g][2]);
                mmabf(acc[mi][2 * g + 1], al[mi], b[g][1], b[g][3]);
            }
        #pragma unroll
        for (int g = 0; g < 4; g++)
            ldsm4(b[g][0], b[g][1], b[g][2], b[g][3], uBlo + boff + g * 16 * 80 + ko);
        #pragma unroll
        for (int mi = 0; mi < 2; mi++)
            #pragma unroll
            for (int g = 0; g < 4; g++) {
                mmabf(acc[mi][2 * g],     ah[mi], b[g][0], b[g][2]);
                mmabf(acc[mi][2 * g + 1], ah[mi], b[g][1], b[g][3]);
            }
    }
}

// ---------------- per-layer GEMM (R12) ----------------
__global__ __launch_bounds__(256, 2)
void k_tgemm(const __nv_bfloat16* __restrict__ aggHi, const __nv_bfloat16* __restrict__ aggLo,
             const float* __restrict__ rootF,
             const __nv_bfloat16* __restrict__ Bhi, const __nv_bfloat16* __restrict__ Blo,
             const float* __restrict__ bias, float* __restrict__ outF) {
    extern __shared__ char smem[];
    float* sbias = (float*)(smem + 2 * STAGE_BYTES);

    const int t = threadIdx.x;
    const int lane = t & 31;
    const int wid = t >> 5;
    const int mw = wid & 3;
    const int nw = wid >> 2;
    const int n0 = blockIdx.x * 128;

    if (t < 128) sbias[t] = bias[t];

    const uint32_t sb0 = s2u(smem);
    const uint32_t sb1 = sb0 + STAGE_BYTES;
    const uint32_t aoff = (uint32_t)((mw * 32 + (lane & 15)) * 80 + (lane >> 4) * 16);
    const uint32_t boff = (uint32_t)((nw * 64 + ((lane >> 3) & 1) * 8 + (lane & 7)) * 80 +
                                     (lane >> 4) * 16);

    float acc[2][8][4];
    #pragma unroll
    for (int mi = 0; mi < 2; mi++)
        #pragma unroll
        for (int ni = 0; ni < 8; ni++)
            #pragma unroll
            for (int q = 0; q < 4; q++) acc[mi][ni][q] = 0.f;

    stage_chunk<4>(sb0, smem, aggHi, aggLo, rootF, Bhi, Blo, 256, n0, 0, t);

    for (int c = 0; c < 8; c++) {
        const uint32_t cur = (c & 1) ? sb1 : sb0;
        if (c + 1 < 8) {
            stage_chunk<4>((c & 1) ? sb0 : sb1, (c & 1) ? smem : (smem + STAGE_BYTES),
                           aggHi, aggLo, rootF, Bhi, Blo, 256, n0, c + 1, t);
            asm volatile("cp.async.wait_group 1;" ::: "memory");
        } else {
            asm volatile("cp.async.wait_group 0;" ::: "memory");
        }
        __syncthreads();
        chunk_mma(cur, aoff, boff, acc);
        __syncthreads();
    }

    #pragma unroll
    for (int mi = 0; mi < 2; mi++) {
        #pragma unroll
        for (int half = 0; half < 2; half++) {
            int node = n0 + mw * 32 + mi * 16 + half * 8 + (lane >> 2);
            if (node < NN) {
                #pragma unroll
                for (int ni = 0; ni < 8; ni++) {
                    int col = nw * 64 + ni * 8 + (lane & 3) * 2;
                    float v0 = fmaxf(acc[mi][ni][half * 2 + 0] + sbias[col], 0.f);
                    float v1 = fmaxf(acc[mi][ni][half * 2 + 1] + sbias[col + 1], 0.f);
                    *(float2*)(outF + (size_t)node * 128 + col) = make_float2(v0, v1);
                }
            }
        }
    }
}

// ---------------- final MLP GEMM with fused 128->2 head (R12) ----------------
__global__ __launch_bounds__(256, 2)
void k_mlp(const float* __restrict__ rootF,
           const __nv_bfloat16* __restrict__ Bhi, const __nv_bfloat16* __restrict__ Blo,
           const float* __restrict__ b1, const float* __restrict__ W2,
           const float* __restrict__ b2, float* __restrict__ out) {
    extern __shared__ char smem[];
    float* sbias = (float*)(smem + 2 * STAGE_BYTES);
    float* sW2   = sbias + 128;
    float* shead = sW2 + 256;

    const int t = threadIdx.x;
    const int lane = t & 31;
    const int wid = t >> 5;
    const int mw = wid & 3;
    const int nw = wid >> 2;
    const int n0 = blockIdx.x * 128;

    if (t < 128) {
        sbias[t] = b1[t];
        sW2[t] = W2[t];
        sW2[128 + t] = W2[128 + t];
        shead[2 * t] = 0.f;
        shead[2 * t + 1] = 0.f;
    }

    const uint32_t sb0 = s2u(smem);
    const uint32_t sb1 = sb0 + STAGE_BYTES;
    const uint32_t aoff = (uint32_t)((mw * 32 + (lane & 15)) * 80 + (lane >> 4) * 16);
    const uint32_t boff = (uint32_t)((nw * 64 + ((lane >> 3) & 1) * 8 + (lane & 7)) * 80 +
                                     (lane >> 4) * 16);

    float acc[2][8][4];
    #pragma unroll
    for (int mi = 0; mi < 2; mi++)
        #pragma unroll
        for (int ni = 0; ni < 8; ni++)
            #pragma unroll
            for (int q = 0; q < 4; q++) acc[mi][ni][q] = 0.f;

    stage_chunk<0>(sb0, smem, nullptr, nullptr, rootF, Bhi, Blo, 128, n0, 0, t);

    for (int c = 0; c < 4; c++) {
        const uint32_t cur = (c & 1) ? sb1 : sb0;
        if (c + 1 < 4) {
            stage_chunk<0>((c & 1) ? sb0 : sb1, (c & 1) ? smem : (smem + STAGE_BYTES),
                           nullptr, nullptr, rootF, Bhi, Blo, 128, n0, c + 1, t);
            asm volatile("cp.async.wait_group 1;" ::: "memory");
        } else {
            asm volatile("cp.async.wait_group 0;" ::: "memory");
        }
        __syncthreads();
        chunk_mma(cur, aoff, boff, acc);
        __syncthreads();
    }

    #pragma unroll
    for (int mi = 0; mi < 2; mi++) {
        #pragma unroll
        for (int half = 0; half < 2; half++) {
            int nl = mw * 32 + mi * 16 + half * 8 + (lane >> 2);
            float p0 = 0.f, p1 = 0.f;
            #pragma unroll
            for (int ni = 0; ni < 8; ni++) {
                int col = nw * 64 + ni * 8 + (lane & 3) * 2;
                float v0 = fmaxf(acc[mi][ni][half * 2 + 0] + sbias[col], 0.f);
                float v1 = fmaxf(acc[mi][ni][half * 2 + 1] + sbias[col + 1], 0.f);
                p0 += v0 * sW2[col] + v1 * sW2[col + 1];
                p1 += v0 * sW2[128 + col] + v1 * sW2[128 + col + 1];
            }
            atomicAdd(&shead[2 * nl], p0);
            atomicAdd(&shead[2 * nl + 1], p1);
        }
    }
    __syncthreads();
    if (t < 128) {
        int n = n0 + t;
        if (n < NN) {
            out[n * 2 + 0] = shead[2 * t] + b2[0];
            out[n * 2 + 1] = shead[2 * t + 1] + b2[1];
        }
    }
}

// ---------------- launch ----------------
extern "C" void kernel_launch(void* const* d_in, const int* in_sizes, int n_in,
                              void* d_out, int out_size) {
    const float* x  = (const float*)d_in[0];
    const int*   ei = (const int*)  d_in[1];
    const float* Wl = (const float*)d_in[2];
    const float* bl = (const float*)d_in[3];
    const float* Wr = (const float*)d_in[4];
    const float* W1 = (const float*)d_in[5];
    const float* b1 = (const float*)d_in[6];
    const float* W2 = (const float*)d_in[7];
    const float* b2 = (const float*)d_in[8];
    float* out = (float*)d_out;

    float *h0, *h1;
    __nv_bfloat16 *aggHi, *aggLo, *bhi, *blo, *w1hi, *w1lo;
    cudaGetSymbolAddress((void**)&h0, g_h0);
    cudaGetSymbolAddress((void**)&h1, g_h1);
    cudaGetSymbolAddress((void**)&aggHi, g_aggHi);
    cudaGetSymbolAddress((void**)&aggLo, g_aggLo);
    cudaGetSymbolAddress((void**)&bhi, g_Bhi);
    cudaGetSymbolAddress((void**)&blo, g_Blo);
    cudaGetSymbolAddress((void**)&w1hi, g_W1hi);
    cudaGetSymbolAddress((void**)&w1lo, g_W1lo);
    float* hb[2] = {h0, h1};

    cudaFuncSetAttribute(k_tgemm, cudaFuncAttributeMaxDynamicSharedMemorySize, TG_SMEM);
    cudaFuncSetAttribute(k_mlp, cudaFuncAttributeMaxDynamicSharedMemorySize, MLP_SMEM);

    // side stream: weight prep concurrent with CSR build
    static cudaStream_t s2 = nullptr;
    static cudaEvent_t eA = nullptr, eB = nullptr;
    if (s2 == nullptr) {
        cudaStreamCreateWithFlags(&s2, cudaStreamNonBlocking);
        cudaEventCreateWithFlags(&eA, cudaEventDisableTiming);
        cudaEventCreateWithFlags(&eB, cudaEventDisableTiming);
    }
    cudaEventRecord(eA, 0);
    cudaStreamWaitEvent(s2, eA, 0);
    k_wprep<<<(LL * 128 * 256 + 128 * 128 + 255) / 256, 256, 0, s2>>>(Wl, Wr, W1);
    cudaEventRecord(eB, s2);

    // CSR build (default stream)
    k_zero_deg<<<(NN + 255) / 256, 256>>>();
    k_hist<<<(EE + 255) / 256, 256>>>(ei);
    k_blocksum<<<(NN + 255) / 256, 256>>>();
    k_scanpart<<<1, 256>>>();
    k_rowptr<<<(NN + 255) / 256, 256>>>();
    k_fill<<<(EE + 255) / 256, 256>>>(ei);
    cudaStreamWaitEvent(0, eB, 0);   // weights ready before first GEMM

    static const int aggrs[LL] = {0, 1, 2, 0, 1, 2, 0, 1, 2, 0, 2, 1};
    const float* hptr = x;
    for (int i = 0; i < LL; i++) {
        switch (aggrs[i]) {
            case 0: k_agg<0><<<AGG_BLOCKS, 256>>>(hptr); break;
            case 1: k_agg<1><<<AGG_BLOCKS, 256>>>(hptr); break;
            default: k_agg<2><<<AGG_BLOCKS, 256>>>(hptr); break;
        }
        float* hout = hb[i & 1];
        k_tgemm<<<GRID_G, 256, TG_SMEM>>>(aggHi, aggLo, hptr,
                                          bhi + (size_t)i * 128 * 256,
                                          blo + (size_t)i * 128 * 256,
                                          bl + (size_t)i * 128, hout);
        hptr = hout;
    }
    k_mlp<<<GRID_G, 256, MLP_SMEM>>>(hptr, w1hi, w1lo, b1, W2, b2, out);
}